// round 6
// baseline (speedup 1.0000x reference)
#include <cuda_runtime.h>
#include <cuda_fp16.h>

// Problem constants
#define BATCH   1024
#define IN_F    4096
#define OUT_F   4096
#define CPB     4        // output columns per CTA (2 per 128-thread group)
#define CAP     160      // bucket capacity per column (mean 41, >13 sigma headroom)

#define NT_BLOCKS (IN_F / 32 * BATCH / 64)   // 2048 transpose blocks (32i x 64b tiles)
#define SC_ILP    8                          // entries per scatter thread

// ---------------- device scratch (no allocations allowed) ----------------
// INVARIANT: g_count == 0 on entry to kernel_launch (static zero-init at load;
// k_spmm re-zeroes each column after reading — exactly one CTA owns a column).
__device__ __half              g_xTh[(size_t)IN_F * BATCH];      // 8MB: xT[r][b] fp16
__device__ int                 g_count[OUT_F];
__device__ unsigned long long  g_bucket[(size_t)OUT_F * CAP];    // {val:hi32, row<<7:lo32}

// packed 2xfp32 FMA (sm_103a FFMA2) — identical per-lane rn rounding
__device__ __forceinline__ void ffma2(unsigned long long& acc,
                                      unsigned long long x2,
                                      unsigned long long v2)
{
    asm("fma.rn.f32x2 %0, %1, %2, %0;" : "+l"(acc) : "l"(x2), "l"(v2));
}

// ---------------- fused prep: bucket-scatter (FIRST blocks) || transpose ---------
__global__ __launch_bounds__(256) void k_prep(const float* __restrict__ x,
                                              const float* __restrict__ vals,
                                              const int*   __restrict__ rows,
                                              const int*   __restrict__ cols,
                                              int nnz, int n_scatter_blocks)
{
    const int bid = blockIdx.x;
    const int tid = threadIdx.x;

    if (bid < n_scatter_blocks) {
        // ---- bucket scatter: entry = {val, row*128} (uint4-index offset) ----
#pragma unroll
        for (int k = 0; k < SC_ILP; k++) {
            int i = bid * 256 * SC_ILP + k * 256 + tid;   // coalesced input reads
            if (i < nnz) {
                int c = cols[i];
                int p = atomicAdd(&g_count[c], 1);
                if (p < CAP) {
                    unsigned long long e =
                        ((unsigned long long)__float_as_uint(vals[i]) << 32) |
                        (unsigned)(rows[i] << 7);
                    g_bucket[(size_t)c * CAP + p] = e;
                }
            }
        }
    } else {
        // ---- transpose x[b][i] fp32 -> xT[i][b] fp16, 32i x 64b tile ----
        // loads 128B-coalesced, STS conflict-free, writes 128B-coalesced half2
        __shared__ float tile[32][65];                    // [i_local][b_local]
        const int tb = bid - n_scatter_blocks;
        const int i0 = (tb & (IN_F / 32 - 1)) * 32;       // 128 tiles along i
        const int b0 = (tb >> 7) * 64;
        const int ix  = tid & 31;
        const int by8 = tid >> 5;                         // 0..7
#pragma unroll
        for (int k = 0; k < 8; k++) {
            int by = by8 + 8 * k;                         // 0..63
            tile[ix][by] = x[(size_t)(b0 + by) * IN_F + i0 + ix];
        }
        __syncthreads();
        const int u  = tid & 31;                          // b-pair index (2u, 2u+1)
        const int il0 = tid >> 5;                         // 0..7
#pragma unroll
        for (int k = 0; k < 4; k++) {
            int il = il0 + 8 * k;                         // 0..31
            __half2 h = __floats2half2_rn(tile[il][2 * u], tile[il][2 * u + 1]);
            *(__half2*)(g_xTh + (size_t)(i0 + il) * BATCH + b0 + 2 * u) = h;
        }
    }
}

// ---------------- main SpMM ----------------
// CTA = 4 columns; two 128-thread groups, each group covers the full 1024-lane
// batch (8 lanes/thread, LDG.128) for 2 columns. fp32x2 register accumulators.
// Self-cleans g_count.
__global__ __launch_bounds__(256, 6) void k_spmm(const float* __restrict__ bias,
                                                 float* __restrict__ out)
{
    __shared__ float accs[CPB][BATCH + 4];            // +4 pad for write-out
    __shared__ unsigned long long sent[CPB * CAP];    // 5.1KB staged entries
    __shared__ int scnt[CPB];
    const int tid  = threadIdx.x;                     // 256
    const int c0   = blockIdx.x * CPB;
    const int grp  = tid >> 7;                        // 0..1 -> columns 2g, 2g+1
    const int lane = tid & 127;                       // 8 lanes: [8*lane, 8*lane+8)

    // read + reset counters (self-cleaning; one CTA owns each column)
    if (tid < CPB) {
        scnt[tid] = min(g_count[c0 + tid], CAP);
        g_count[c0 + tid] = 0;
    }
    __syncthreads();

    // stage entries, zero-padded to a multiple of 2 (val=0 contributes 0; off=0 valid)
#pragma unroll
    for (int cl = 0; cl < CPB; cl++) {
        const int cnt  = scnt[cl];
        const int pcnt = (cnt + 1) & ~1;
        for (int j = tid; j < pcnt; j += 256)
            sent[cl * CAP + j] = (j < cnt)
                ? __ldg(&g_bucket[(size_t)(c0 + cl) * CAP + j]) : 0ull;
    }
    __syncthreads();

    const uint4* xb = ((const uint4*)g_xTh) + lane;   // this thread's 16B slice

#pragma unroll
    for (int cc = 0; cc < 2; cc++) {
        const int cl   = grp * 2 + cc;
        const int pcnt = (scnt[cl] + 1) & ~1;
        const float bc = __ldg(&bias[c0 + cl]);
        float2 b2 = make_float2(bc, bc);
        unsigned long long a01 = *(const unsigned long long*)&b2;
        unsigned long long a23 = a01, a45 = a01, a67 = a01;

        const ulonglong2* sent2 = (const ulonglong2*)(sent + cl * CAP);
        for (int jp = 0; jp < (pcnt >> 1); jp++) {
            const ulonglong2 e2 = sent2[jp];          // LDS.128: two entries
            const unsigned offA = (unsigned)(e2.x & 0xffffffffull);
            const unsigned offB = (unsigned)(e2.y & 0xffffffffull);
            const uint4 ha = __ldg(xb + offA);        // 8 fp16 lanes, 16B
            const uint4 hb = __ldg(xb + offB);        // second entry in flight

#pragma unroll
            for (int k = 0; k < 2; k++) {
                const uint4 h = k ? hb : ha;
                const float v = __uint_as_float(
                    (unsigned)((k ? e2.y : e2.x) >> 32));
                float2 vp = make_float2(v, v);
                const unsigned long long v2 = *(const unsigned long long*)&vp;
                float2 f0 = __half22float2(*(const __half2*)&h.x);
                float2 f1 = __half22float2(*(const __half2*)&h.y);
                float2 f2 = __half22float2(*(const __half2*)&h.z);
                float2 f3 = __half22float2(*(const __half2*)&h.w);
                ffma2(a01, *(const unsigned long long*)&f0, v2);
                ffma2(a23, *(const unsigned long long*)&f1, v2);
                ffma2(a45, *(const unsigned long long*)&f2, v2);
                ffma2(a67, *(const unsigned long long*)&f3, v2);
            }
        }
        const int b8 = lane * 8;
        float2 r01 = *(const float2*)&a01, r23 = *(const float2*)&a23;
        float2 r45 = *(const float2*)&a45, r67 = *(const float2*)&a67;
        *(float4*)&accs[cl][b8]     = make_float4(r01.x, r01.y, r23.x, r23.y);
        *(float4*)&accs[cl][b8 + 4] = make_float4(r45.x, r45.y, r67.x, r67.y);
    }
    __syncthreads();

    // write-back: consecutive threads -> consecutive out addresses (16B granules)
    for (int idx = tid; idx < CPB * BATCH; idx += 256) {
        int cl = idx & (CPB - 1);
        int b  = idx >> 2;  // log2(CPB)
        out[(size_t)b * OUT_F + c0 + cl] = accs[cl][b];
    }
}

// ---------------- entry point ----------------
extern "C" void kernel_launch(void* const* d_in, const int* in_sizes, int n_in,
                              void* d_out, int out_size)
{
    const float* x      = (const float*)d_in[0];
    const float* values = (const float*)d_in[1];
    const float* bias   = (const float*)d_in[2];
    const int*   rows   = (const int*)d_in[3];
    const int*   cols   = (const int*)d_in[4];
    float*       out    = (float*)d_out;
    const int    nnz    = in_sizes[1];

    const int n_scatter_blocks = (nnz + 256 * SC_ILP - 1) / (256 * SC_ILP);

    k_prep<<<NT_BLOCKS + n_scatter_blocks, 256>>>(x, values, rows, cols,
                                                  nnz, n_scatter_blocks);
    k_spmm<<<OUT_F / CPB, 256>>>(bias, out);
}